// round 10
// baseline (speedup 1.0000x reference)
#include <cuda_runtime.h>
#include <cstdint>

// ---------------------------------------------------------------------------
// SE3Net (all l=0): K(r) depends only on pair distance; zero for r>=4.5.
// K0 prep: per-layer SMEM transpose of w_h -> bf16x2 g_whT[l][c][q*16+t]
//          (word t packs (w[2*(13q+t)][c], w[2*(13q+t)+1][c])). Coalesced
//          read AND write.
// K1 mlp : 8 blocks x 416 threads (NPTS=32, TM=4). Weights in EXPLICIT uint4
//          registers (no arrays -> no local spill), 4x LDG.128 prefetch one
//          layer ahead, h broadcast in SMEM, shfl q-combine, 1 barrier/layer.
// K2 conv: 144 blocks x 512 threads = ONE wave. Warp-per-atom, NN table
//          lookup, exact 2-addend atomics, fused relu+mean+linear epilogue.
// ---------------------------------------------------------------------------

#define NPTS    32
#define OCP     52
#define CIN     23
#define FSTR    24
#define NB      286
#define BATCH   4
#define HDIM    100
#define CPAD    104
#define NLAYERS 49
#define RMAX    4.5f
#define DELTA   (RMAX / (float)(NPTS - 1))
#define INV_DELTA ((float)(NPTS - 1) / RMAX)

#define TM 4
#define GRID_MLP (NPTS / TM)        // 8
#define MLP_THREADS 416             // 13 warps

#define ATOMS_PB 16
#define CONV_THREADS 512
#define NBXC ((NB + ATOMS_PB - 1) / ATOMS_PB)   // 18
#define JSPLIT 2
#define JHALF (NB / JSPLIT)                     // 143
#define BLK_PER_BATCH (NBXC * JSPLIT)           // 36

typedef unsigned long long ull;

__device__ __align__(16) float    g_table[NPTS * OCP];
__device__ __align__(16) uint32_t g_whT[NLAYERS * CPAD * 64];   // 1.3 MB
__device__ float g_rows[BATCH * NB * 2];
__device__ int   g_ctr[BATCH];

__device__ __forceinline__ ull ffma2(ull a, ull b, ull c) {
    ull d;
    asm("fma.rn.f32x2 %0, %1, %2, %3;" : "=l"(d) : "l"(a), "l"(b), "l"(c));
    return d;
}
__device__ __forceinline__ ull add2(ull a, ull b) {
    ull d;
    asm("add.rn.f32x2 %0, %1, %2;" : "=l"(d) : "l"(a), "l"(b));
    return d;
}
__device__ __forceinline__ ull pack2(float lo, float hi) {
    ull d;
    asm("mov.b64 %0, {%1, %2};" : "=l"(d) : "f"(lo), "f"(hi));
    return d;
}
__device__ __forceinline__ float2 unpack2(ull v) {
    float lo, hi;
    asm("mov.b64 {%0, %1}, %2;" : "=f"(lo), "=f"(hi) : "l"(v));
    return make_float2(lo, hi);
}
__device__ __forceinline__ float bump(float x) {
    float ax = fabsf(x);
    if (ax >= 1.0f) return 0.0f;
    float c = cosf(1.5707963267948966f * x);
    return c * c;
}

// ---------------------------------------------------------------------------
// Kernel 0: prep. One block per layer; SMEM transpose; coalesced in and out.
// ---------------------------------------------------------------------------
__global__ void __launch_bounds__(256) prep_kernel(const float* __restrict__ w_h)
{
    __shared__ float sw[HDIM * HDIM];           // 40 KB
    const int tid = threadIdx.x;
    const int l = blockIdx.x;

    const float4* src = reinterpret_cast<const float4*>(
        w_h + (size_t)l * (HDIM * HDIM));
#pragma unroll
    for (int k = 0; k < (HDIM * HDIM) / 4 / 256 + 1; k++) {
        int idx = k * 256 + tid;
        if (idx < (HDIM * HDIM) / 4)
            reinterpret_cast<float4*>(sw)[idx] = src[idx];
    }
    __syncthreads();

    uint32_t* dst = g_whT + (size_t)l * (CPAD * 64);
    for (int idx = tid; idx < CPAD * 64; idx += 256) {
        int c = idx >> 6;
        int rem = idx & 63;
        int q = rem >> 4;
        int t = rem & 15;
        float lo = 0.0f, hi = 0.0f;
        if (c < HDIM && t < 13) {
            int j = 2 * (13 * q + t);
            if (j < HDIM)     lo = sw[j * HDIM + c];
            if (j + 1 < HDIM) hi = sw[(j + 1) * HDIM + c];
        }
        uint32_t r;
        asm("cvt.rn.bf16x2.f32 %0, %1, %2;" : "=r"(r) : "f"(hi), "f"(lo));
        dst[idx] = r;                           // consecutive tid -> coalesced
    }
}

// ---------------------------------------------------------------------------
// Kernel 1: grid MLP. Explicit-register weights; one barrier per layer.
// ---------------------------------------------------------------------------
__global__ void __launch_bounds__(MLP_THREADS, 1) mlp_table_kernel(
    const float* __restrict__ w_in,    // [3,100]
    const float* __restrict__ w_out)   // [100,46]
{
    __shared__ __align__(16) ull h2[2][CPAD][2];   // [buf][c][rowpair]

    const int tid = threadIdx.x;
    const int wrp = tid >> 5;
    const int ln  = tid & 31;
    const int q   = ln >> 3;            // j-quarter 0..3
    const int c   = wrp * 8 + (ln & 7); // column 0..103
    const int m0  = blockIdx.x * TM;

    // prefetch layer-0 weights: 4 x LDG.128, explicit registers
    const uint4* wp = reinterpret_cast<const uint4*>(
        g_whT + ((size_t)c * 64 + q * 16));
    uint4 wc0 = wp[0], wc1 = wp[1], wc2 = wp[2], wc3 = wp[3];

    // ---- input layer: basis -> h (q==0 lanes cover each c once) ----
    if (q == 0) {
        ull hv0 = 0ULL, hv1 = 0ULL;
        if (c < HDIM) {
            const float inv_sqrt3 = 0.57735026918962576f;
            float wi0 = w_in[c], wi1 = w_in[HDIM + c], wi2 = w_in[2 * HDIM + c];
            float v[TM];
#pragma unroll
            for (int r = 0; r < TM; r++) {
                float rr = (float)(m0 + r) * DELTA;
                float b0 = bump(rr * (1.0f / 1.5f));
                float b1 = bump((rr - 1.5f) * (1.0f / 1.5f));
                float b2 = bump((rr - 3.0f) * (1.0f / 1.5f));
                float a = (b0 * wi0 + b1 * wi1 + b2 * wi2) * inv_sqrt3;
                v[r] = fmaxf(a, 0.0f);
            }
            hv0 = pack2(v[0], v[1]);
            hv1 = pack2(v[2], v[3]);
        }
        h2[0][c][0] = hv0;
        h2[0][c][1] = hv1;
    }
    __syncthreads();

// One MAC step: weight word W packs columns? NO — packs j-pair (2*(13q+t),
// 2*(13q+t)+1) for THIS c. Load h for both j, fma into rowpair accumulators.
#define MLP_STEP(W, T)                                                        \
    {                                                                         \
        ulonglong2 hA = *reinterpret_cast<const ulonglong2*>(                 \
            &h2[cur][2 * (13 * q + (T))][0]);                                 \
        ulonglong2 hB = *reinterpret_cast<const ulonglong2*>(                 \
            &h2[cur][2 * (13 * q + (T)) + 1][0]);                             \
        float flo = __uint_as_float((W) << 16);                               \
        float fhi = __uint_as_float((W) & 0xFFFF0000u);                       \
        ull plo = pack2(flo, flo);                                            \
        ull phi = pack2(fhi, fhi);                                            \
        acc0 = ffma2(hA.x, plo, acc0);                                        \
        acc1 = ffma2(hA.y, plo, acc1);                                        \
        acc0 = ffma2(hB.x, phi, acc0);                                        \
        acc1 = ffma2(hB.y, phi, acc1);                                        \
    }

    int cur = 0;
#pragma unroll 1
    for (int l = 0; l < NLAYERS; l++) {
        // prefetch next layer (explicit regs; guarded)
        uint4 wn0, wn1, wn2, wn3;
        if (l + 1 < NLAYERS) {
            const uint4* np = reinterpret_cast<const uint4*>(
                g_whT + (((size_t)(l + 1) * CPAD + c) * 64 + q * 16));
            wn0 = np[0]; wn1 = np[1]; wn2 = np[2]; wn3 = np[3];
        }

        ull acc0 = 0ULL, acc1 = 0ULL;
        MLP_STEP(wc0.x, 0)  MLP_STEP(wc0.y, 1)  MLP_STEP(wc0.z, 2)
        MLP_STEP(wc0.w, 3)  MLP_STEP(wc1.x, 4)  MLP_STEP(wc1.y, 5)
        MLP_STEP(wc1.z, 6)  MLP_STEP(wc1.w, 7)  MLP_STEP(wc2.x, 8)
        MLP_STEP(wc2.y, 9)  MLP_STEP(wc2.z, 10) MLP_STEP(wc2.w, 11)
        MLP_STEP(wc3.x, 12)

        // combine 4 q-partials (lane bits 3,4)
        acc0 = add2(acc0, __shfl_xor_sync(0xffffffffu, acc0, 8));
        acc1 = add2(acc1, __shfl_xor_sync(0xffffffffu, acc1, 8));
        acc0 = add2(acc0, __shfl_xor_sync(0xffffffffu, acc0, 16));
        acc1 = add2(acc1, __shfl_xor_sync(0xffffffffu, acc1, 16));

        if (q == 0) {
            ull o0 = 0ULL, o1 = 0ULL;
            if (c < HDIM) {
                float2 v0 = unpack2(acc0), v1 = unpack2(acc1);
                o0 = pack2(fmaxf(v0.x * 0.1f, 0.f), fmaxf(v0.y * 0.1f, 0.f));
                o1 = pack2(fmaxf(v1.x * 0.1f, 0.f), fmaxf(v1.y * 0.1f, 0.f));
            }
            h2[cur ^ 1][c][0] = o0;     // pads stay exactly zero
            h2[cur ^ 1][c][1] = o1;
        }
        __syncthreads();

        wc0 = wn0; wc1 = wn1; wc2 = wn2; wc3 = wn3;
        cur ^= 1;
    }
#undef MLP_STEP

    // ---- output layer: 46 outputs x 4 rows = 184 threads ----
    if (tid < 2 * CIN * TM) {
        int o = tid % (2 * CIN);
        int r = tid / (2 * CIN);
        // float layout of h2[cur]: c*4 + rowpair*2 + (r&1)
        const float* hp = reinterpret_cast<const float*>(&h2[cur][0][0])
                          + (r >> 1) * 2 + (r & 1);
        float acc = 0.0f;
#pragma unroll 4
        for (int j = 0; j < HDIM; j++)
            acc = fmaf(hp[j * 4], w_out[j * (2 * CIN) + o], acc);
        const float SCALE = 0.1f * 0.28209479177387814f * 0.5f;
        int co = o % CIN, oo = o / CIN;
        g_table[(m0 + r) * OCP + co * 2 + oo] = acc * SCALE;
    }
    for (int z = tid; z < TM * (OCP - 2 * CIN); z += MLP_THREADS) {
        int r = z / (OCP - 2 * CIN);
        int pos = 2 * CIN + z % (OCP - 2 * CIN);
        g_table[(m0 + r) * OCP + pos] = 0.0f;
    }
}

// ---------------------------------------------------------------------------
// Kernel 2: conv, one wave (144 blocks x 512 threads), fused epilogue.
// ---------------------------------------------------------------------------
__global__ void __launch_bounds__(CONV_THREADS) conv_kernel(
    const float* __restrict__ features,   // [B,N,23]
    const float* __restrict__ geometry,   // [B,N,3]
    const float* __restrict__ lin_w,      // [2]
    const float* __restrict__ lin_b,      // [1]
    float* __restrict__ out)              // [B]
{
    __shared__ __align__(16) float table_s[NPTS * OCP];    // 6.7 KB
    __shared__ __align__(16) float feat_s[JHALF * FSTR];   // 13.7 KB
    __shared__ __align__(16) float geo_s[NB * 4];          // 4.6 KB
    __shared__ float red0[CONV_THREADS];
    __shared__ float red1[CONV_THREADS];
    __shared__ int last_flag;

    const int tid = threadIdx.x;
    const int wrp = tid >> 5;
    const int ln  = tid & 31;
    const int b = blockIdx.z;
    const int js = blockIdx.y;
    const int jbeg = js * JHALF;

    if (tid < (NPTS * OCP) / 4)                 // 416 float4: one pass
        reinterpret_cast<float4*>(table_s)[tid] =
            reinterpret_cast<const float4*>(g_table)[tid];
    const float* fb = features + (size_t)b * NB * CIN;
    for (int jr = wrp; jr < JHALF; jr += CONV_THREADS / 32) {
        if (ln < FSTR)
            feat_s[jr * FSTR + ln] =
                (ln < CIN) ? fb[(jbeg + jr) * CIN + ln] : 0.0f;
    }
    const float* gb = geometry + (size_t)b * NB * 3;
    for (int k = tid; k < NB * 4; k += CONV_THREADS) {
        int j = k >> 2, d = k & 3;
        geo_s[k] = (d < 3) ? gb[j * 3 + d] : 0.0f;
    }
    __syncthreads();

    const int i = blockIdx.x * ATOMS_PB + wrp;
    const bool valid = (i < NB);
    float gx = 0.f, gy = 0.f, gz = 0.f;
    if (valid) { gx = geo_s[i * 4]; gy = geo_s[i * 4 + 1]; gz = geo_s[i * 4 + 2]; }

    ull acc = 0ULL;
    for (int jr = ln; jr < JHALF; jr += 32) {
        float4 g4 = *reinterpret_cast<const float4*>(geo_s + (jbeg + jr) * 4);
        float dx = g4.x - gx, dy = g4.y - gy, dz = g4.z - gz;
        float r = sqrtf(fmaf(dx, dx, fmaf(dy, dy, fmaf(dz, dz, 1e-12f))));
        int u = __float2int_rn(r * INV_DELTA);
        if (valid && u < NPTS) {
            const ulonglong2* __restrict__ T =
                reinterpret_cast<const ulonglong2*>(table_s + u * OCP);
            const float4* __restrict__ f4 =
                reinterpret_cast<const float4*>(feat_s + jr * FSTR);
            ull d0 = 0ULL, d1 = 0ULL;
#pragma unroll
            for (int k = 0; k < 6; k++) {
                float4 f = f4[k];
                ulonglong2 t0 = T[2 * k];
                ulonglong2 t1 = T[2 * k + 1];
                d0 = ffma2(t0.x, pack2(f.x, f.x), d0);
                d1 = ffma2(t0.y, pack2(f.y, f.y), d1);
                d0 = ffma2(t1.x, pack2(f.z, f.z), d0);
                d1 = ffma2(t1.y, pack2(f.w, f.w), d1);
            }
            acc = add2(acc, add2(d0, d1));
        }
    }

    float2 av = unpack2(acc);
    float a0 = av.x, a1 = av.y;
#pragma unroll
    for (int off = 16; off > 0; off >>= 1) {
        a0 += __shfl_xor_sync(0xffffffffu, a0, off);
        a1 += __shfl_xor_sync(0xffffffffu, a1, off);
    }
    if (ln == 0 && valid) {
        // exactly 2 addends per row (JSPLIT=2): commutative -> deterministic
        atomicAdd(&g_rows[(b * NB + i) * 2 + 0], a0);
        atomicAdd(&g_rows[(b * NB + i) * 2 + 1], a1);
    }

    // ---- fused epilogue: last block of this batch does relu+mean+linear ----
    __threadfence();
    __syncthreads();
    if (tid == 0)
        last_flag = (atomicAdd(&g_ctr[b], 1) == BLK_PER_BATCH - 1) ? 1 : 0;
    __syncthreads();
    if (last_flag) {
        __threadfence();
        float s0 = 0.f, s1 = 0.f;
        for (int k = tid; k < NB; k += CONV_THREADS) {
            s0 += fmaxf(g_rows[(b * NB + k) * 2 + 0], 0.0f);
            s1 += fmaxf(g_rows[(b * NB + k) * 2 + 1], 0.0f);
            g_rows[(b * NB + k) * 2 + 0] = 0.0f;    // reset for next replay
            g_rows[(b * NB + k) * 2 + 1] = 0.0f;
        }
        red0[tid] = s0; red1[tid] = s1;
        __syncthreads();
#pragma unroll
        for (int s = CONV_THREADS / 2; s > 0; s >>= 1) {
            if (tid < s) { red0[tid] += red0[tid + s]; red1[tid] += red1[tid + s]; }
            __syncthreads();
        }
        if (tid == 0) {
            out[b] = (red0[0] * lin_w[0] + red1[0] * lin_w[1])
                     * (1.0f / (float)NB) + lin_b[0];
            g_ctr[b] = 0;                           // reset for next replay
        }
    }
}

// ---------------------------------------------------------------------------
extern "C" void kernel_launch(void* const* d_in, const int* in_sizes, int n_in,
                              void* d_out, int out_size) {
    int o = 0;
    if (n_in >= 4 && in_sizes[2] == 1) o = 1;   // num_atoms scalar present

    const float* features = (const float*)d_in[0];
    const float* geometry = (const float*)d_in[1];
    const float* w_in     = (const float*)d_in[2 + o];
    const float* w_h      = (const float*)d_in[3 + o];
    const float* w_out    = (const float*)d_in[4 + o];
    const float* lin_w    = (const float*)d_in[5 + o];
    const float* lin_b    = (const float*)d_in[6 + o];

    prep_kernel<<<NLAYERS, 256>>>(w_h);
    mlp_table_kernel<<<GRID_MLP, MLP_THREADS>>>(w_in, w_out);
    conv_kernel<<<dim3(NBXC, JSPLIT, BATCH), CONV_THREADS>>>(
        features, geometry, lin_w, lin_b, (float*)d_out);
}

// round 11
// speedup vs baseline: 1.3800x; 1.3800x over previous
#include <cuda_runtime.h>
#include <cstdint>

// ---------------------------------------------------------------------------
// SE3Net fused single-kernel, 144 blocks = all co-resident (<=148 SMs):
//   blocks 0..127  : conv role (32/batch, 9 warps -> 9 atoms each, full j).
//                    Stage feat/geo immediately -> spin on table flag ->
//                    copy table -> mainloop -> per-batch fused epilogue.
//   blocks 128..143: MLP role = R6's proven kernel verbatim (fp32 weights in
//                    registers via scalar LDG lookahead, SMEM part-combine),
//                    NPTS=64, TM=4. Last MLP block releases the flag.
// All flags/counters self-reset for graph replay. Deterministic.
// ---------------------------------------------------------------------------

#define NPTS    64
#define OCP     52
#define CIN     23
#define FSTR    24
#define NB      286
#define BATCH   4
#define HDIM    100
#define NLAYERS 49
#define RMAX    4.5f
#define DELTA   (RMAX / (float)(NPTS - 1))
#define INV_DELTA ((float)(NPTS - 1) / RMAX)

#define TM 4
#define GRID_MLP (NPTS / TM)            // 16
#define QD 4
#define JPQ (HDIM / QD)                 // 25
#define THREADS 400                     // 12.5 warps (both roles)

#define ATOMS_PB 9
#define BLK_PER_BATCH 32                // 32*9 = 288 >= 286
#define NCONV (BLK_PER_BATCH * BATCH)   // 128
#define NGRID (NCONV + GRID_MLP)        // 144

typedef unsigned long long ull;

__device__ __align__(16) float g_table[NPTS * OCP];
__device__ float g_rows[BATCH * NB * 2];
__device__ int   g_ctr[BATCH];
__device__ int   g_flag;
__device__ int   g_mlp_done;
__device__ int   g_done;

__device__ __forceinline__ ull ffma2(ull a, ull b, ull c) {
    ull d;
    asm("fma.rn.f32x2 %0, %1, %2, %3;" : "=l"(d) : "l"(a), "l"(b), "l"(c));
    return d;
}
__device__ __forceinline__ ull add2(ull a, ull b) {
    ull d;
    asm("add.rn.f32x2 %0, %1, %2;" : "=l"(d) : "l"(a), "l"(b));
    return d;
}
__device__ __forceinline__ ull pack2(float lo, float hi) {
    ull d;
    asm("mov.b64 %0, {%1, %2};" : "=l"(d) : "f"(lo), "f"(hi));
    return d;
}
__device__ __forceinline__ float2 unpack2(ull v) {
    float lo, hi;
    asm("mov.b64 {%0, %1}, %2;" : "=f"(lo), "=f"(hi) : "l"(v));
    return make_float2(lo, hi);
}
__device__ __forceinline__ float bump(float x) {
    float ax = fabsf(x);
    if (ax >= 1.0f) return 0.0f;
    float c = cosf(1.5707963267948966f * x);
    return c * c;
}

__global__ void __launch_bounds__(THREADS) fused_kernel(
    const float* __restrict__ features,   // [B,N,23]
    const float* __restrict__ geometry,   // [B,N,3]
    const float* __restrict__ w_in,       // [3,100]
    const float* __restrict__ w_h,        // [49,100,100]
    const float* __restrict__ w_out,      // [100,46]
    const float* __restrict__ lin_w,      // [2]
    const float* __restrict__ lin_b,      // [1]
    float* __restrict__ out)              // [B]
{
    extern __shared__ __align__(16) float dyn[];   // conv staging only
    __shared__ __align__(16) ull h2[2][HDIM][2];   // mlp: [buf][j][rowpair]
    __shared__ __align__(16) ull part[QD][HDIM][2];
    __shared__ float red0[THREADS];
    __shared__ float red1[THREADS];
    __shared__ int last_flag;

    const int tid = threadIdx.x;
    const int wrp = tid >> 5;
    const int ln  = tid & 31;
    const int bid = blockIdx.x;

    // =======================================================================
    // MLP role — R6's kernel verbatim (NPTS=64 -> 16 blocks).
    // =======================================================================
    if (bid >= NCONV) {
        const int m0 = (bid - NCONV) * TM;
        const int q  = tid / HDIM;      // 0..3
        const int c  = tid % HDIM;      // 0..99
        const int j0 = q * JPQ;

        float wcur[JPQ], wnxt[JPQ];
        {
            const float* base = w_h + c;
#pragma unroll
            for (int jj = 0; jj < JPQ; jj++)
                wcur[jj] = base[(j0 + jj) * HDIM];
        }

        if (tid < HDIM) {
            const float inv_sqrt3 = 0.57735026918962576f;
            float wi0 = w_in[tid], wi1 = w_in[HDIM + tid],
                  wi2 = w_in[2 * HDIM + tid];
            float v[TM];
#pragma unroll
            for (int r = 0; r < TM; r++) {
                float rr = (float)(m0 + r) * DELTA;
                float b0 = bump(rr * (1.0f / 1.5f));
                float b1 = bump((rr - 1.5f) * (1.0f / 1.5f));
                float b2 = bump((rr - 3.0f) * (1.0f / 1.5f));
                float a = (b0 * wi0 + b1 * wi1 + b2 * wi2) * inv_sqrt3;
                v[r] = fmaxf(a, 0.0f);
            }
            h2[0][tid][0] = pack2(v[0], v[1]);
            h2[0][tid][1] = pack2(v[2], v[3]);
        }
        __syncthreads();

        int cur = 0;
#pragma unroll 1
        for (int l = 0; l < NLAYERS; l++) {
            if (l + 1 < NLAYERS) {
                const float* base = w_h + (size_t)(l + 1) * (HDIM * HDIM) + c;
#pragma unroll
                for (int jj = 0; jj < JPQ; jj++)
                    wnxt[jj] = base[(j0 + jj) * HDIM];
            }

            ull a0 = 0, a1 = 0, b0 = 0, b1 = 0;
#pragma unroll
            for (int jj = 0; jj < JPQ; jj += 2) {
                {
                    ulonglong2 hv = *reinterpret_cast<const ulonglong2*>(
                        &h2[cur][j0 + jj][0]);
                    ull pw = pack2(wcur[jj], wcur[jj]);
                    a0 = ffma2(hv.x, pw, a0);
                    a1 = ffma2(hv.y, pw, a1);
                }
                if (jj + 1 < JPQ) {
                    ulonglong2 hv = *reinterpret_cast<const ulonglong2*>(
                        &h2[cur][j0 + jj + 1][0]);
                    ull pw = pack2(wcur[jj + 1], wcur[jj + 1]);
                    b0 = ffma2(hv.x, pw, b0);
                    b1 = ffma2(hv.y, pw, b1);
                }
            }
            part[q][c][0] = add2(a0, b0);
            part[q][c][1] = add2(a1, b1);
            __syncthreads();

            if (tid < HDIM) {
                ull s0 = add2(add2(part[0][tid][0], part[1][tid][0]),
                              add2(part[2][tid][0], part[3][tid][0]));
                ull s1 = add2(add2(part[0][tid][1], part[1][tid][1]),
                              add2(part[2][tid][1], part[3][tid][1]));
                float2 v0 = unpack2(s0), v1 = unpack2(s1);
                h2[cur ^ 1][tid][0] = pack2(fmaxf(v0.x * 0.1f, 0.0f),
                                            fmaxf(v0.y * 0.1f, 0.0f));
                h2[cur ^ 1][tid][1] = pack2(fmaxf(v1.x * 0.1f, 0.0f),
                                            fmaxf(v1.y * 0.1f, 0.0f));
            }
            __syncthreads();

            if (l + 1 < NLAYERS) {
#pragma unroll
                for (int jj = 0; jj < JPQ; jj++) wcur[jj] = wnxt[jj];
            }
            cur ^= 1;
        }

        // output layer: 46 cols x 4 rows = 184 threads; zero pads
        if (tid < 2 * CIN * TM) {
            int o = tid % (2 * CIN);
            int r = tid / (2 * CIN);
            const float* hp = reinterpret_cast<const float*>(&h2[cur][0][0])
                              + (r >> 1) * 2 + (r & 1);
            float acc = 0.0f;
#pragma unroll 4
            for (int j = 0; j < HDIM; j++)
                acc = fmaf(hp[j * 4], w_out[j * (2 * CIN) + o], acc);
            const float SCALE = 0.1f * 0.28209479177387814f * 0.5f;
            int co = o % CIN, oo = o / CIN;
            g_table[(m0 + r) * OCP + co * 2 + oo] = acc * SCALE;
        }
        for (int z = tid; z < TM * (OCP - 2 * CIN); z += THREADS) {
            int r = z / (OCP - 2 * CIN);
            int pos = 2 * CIN + z % (OCP - 2 * CIN);
            g_table[(m0 + r) * OCP + pos] = 0.0f;
        }

        __threadfence();
        __syncthreads();
        if (tid == 0) {
            int prev = atomicAdd(&g_mlp_done, 1);
            if (prev == GRID_MLP - 1) atomicExch(&g_flag, 1);
        }
        return;
    }

    // =======================================================================
    // Conv role
    // =======================================================================
    float* table_s = dyn;                       // NPTS*OCP = 3328 floats
    float* feat_s  = dyn + NPTS * OCP;          // NB*FSTR  = 6864
    float* geo_s   = feat_s + NB * FSTR;        // NB*4     = 1144

    const int b = bid >> 5;                     // 32 blocks per batch
    const int grp = bid & 31;

    // stage features/geometry NOW (independent of MLP)
    const float* fb = features + (size_t)b * NB * CIN;
    if (wrp < 12) {                             // full warps only
        for (int jr = wrp; jr < NB; jr += 12) {
            if (ln < FSTR)
                feat_s[jr * FSTR + ln] = (ln < CIN) ? fb[jr * CIN + ln] : 0.0f;
        }
    }
    const float* gb = geometry + (size_t)b * NB * 3;
    for (int k = tid; k < NB * 4; k += THREADS) {
        int j = k >> 2, d = k & 3;
        geo_s[k] = (d < 3) ? gb[j * 3 + d] : 0.0f;
    }

    // wait for the table
    if (tid == 0) {
        int v;
        do {
            asm volatile("ld.acquire.gpu.global.s32 %0, [%1];"
                         : "=r"(v) : "l"(&g_flag) : "memory");
            if (!v) __nanosleep(200);
        } while (!v);
    }
    __syncthreads();

    // copy table (832 float4)
    for (int k = tid; k < (NPTS * OCP) / 4; k += THREADS)
        reinterpret_cast<float4*>(table_s)[k] =
            reinterpret_cast<const float4*>(g_table)[k];
    __syncthreads();

    // mainloop: warp-per-atom (warps 0..8), full j range -> direct store
    const int i = grp * ATOMS_PB + wrp;
    if (wrp < ATOMS_PB && i < NB) {
        float gx = geo_s[i * 4], gy = geo_s[i * 4 + 1], gz = geo_s[i * 4 + 2];
        ull acc = 0ULL;
        for (int j = ln; j < NB; j += 32) {
            float4 g4 = *reinterpret_cast<const float4*>(geo_s + j * 4);
            float dx = g4.x - gx, dy = g4.y - gy, dz = g4.z - gz;
            float r = sqrtf(fmaf(dx, dx, fmaf(dy, dy, fmaf(dz, dz, 1e-12f))));
            int u = __float2int_rn(r * INV_DELTA);
            if (u < NPTS) {
                const ulonglong2* __restrict__ T =
                    reinterpret_cast<const ulonglong2*>(table_s + u * OCP);
                const float4* __restrict__ f4 =
                    reinterpret_cast<const float4*>(feat_s + j * FSTR);
                ull d0 = 0ULL, d1 = 0ULL;
#pragma unroll
                for (int k = 0; k < 6; k++) {
                    float4 f = f4[k];
                    ulonglong2 t0 = T[2 * k];
                    ulonglong2 t1 = T[2 * k + 1];
                    d0 = ffma2(t0.x, pack2(f.x, f.x), d0);
                    d1 = ffma2(t0.y, pack2(f.y, f.y), d1);
                    d0 = ffma2(t1.x, pack2(f.z, f.z), d0);
                    d1 = ffma2(t1.y, pack2(f.w, f.w), d1);
                }
                acc = add2(acc, add2(d0, d1));
            }
        }
        float2 av = unpack2(acc);
        float a0 = av.x, a1 = av.y;
#pragma unroll
        for (int off = 16; off > 0; off >>= 1) {
            a0 += __shfl_xor_sync(0xffffffffu, a0, off);
            a1 += __shfl_xor_sync(0xffffffffu, a1, off);
        }
        if (ln == 0) {                      // single writer: direct store
            g_rows[(b * NB + i) * 2 + 0] = fmaxf(a0, 0.0f);
            g_rows[(b * NB + i) * 2 + 1] = fmaxf(a1, 0.0f);
        }
    }

    // fused epilogue: last block of this batch does mean + linear
    __threadfence();
    __syncthreads();
    if (tid == 0)
        last_flag = (atomicAdd(&g_ctr[b], 1) == BLK_PER_BATCH - 1) ? 1 : 0;
    __syncthreads();
    if (last_flag) {
        __threadfence();
        float s0 = 0.f, s1 = 0.f;
        for (int k = tid; k < NB; k += THREADS) {
            s0 += g_rows[(b * NB + k) * 2 + 0];
            s1 += g_rows[(b * NB + k) * 2 + 1];
        }
        red0[tid] = s0; red1[tid] = s1;
        __syncthreads();
        if (tid < THREADS - 256) {              // fold 400 -> 256
            red0[tid] += red0[tid + 256];
            red1[tid] += red1[tid + 256];
        }
        __syncthreads();
#pragma unroll
        for (int s = 128; s > 0; s >>= 1) {
            if (tid < s) { red0[tid] += red0[tid + s]; red1[tid] += red1[tid + s]; }
            __syncthreads();
        }
        if (tid == 0) {
            out[b] = (red0[0] * lin_w[0] + red1[0] * lin_w[1])
                     * (1.0f / (float)NB) + lin_b[0];
            g_ctr[b] = 0;                       // replay reset
            int p = atomicAdd(&g_done, 1);
            if (p == BATCH - 1) {               // final replay reset
                g_flag = 0;
                g_mlp_done = 0;
                g_done = 0;
            }
        }
    }
}

// ---------------------------------------------------------------------------
extern "C" void kernel_launch(void* const* d_in, const int* in_sizes, int n_in,
                              void* d_out, int out_size) {
    int o = 0;
    if (n_in >= 4 && in_sizes[2] == 1) o = 1;   // num_atoms scalar present

    const float* features = (const float*)d_in[0];
    const float* geometry = (const float*)d_in[1];
    const float* w_in     = (const float*)d_in[2 + o];
    const float* w_h      = (const float*)d_in[3 + o];
    const float* w_out    = (const float*)d_in[4 + o];
    const float* lin_w    = (const float*)d_in[5 + o];
    const float* lin_b    = (const float*)d_in[6 + o];

    const int dsmem = (NPTS * OCP + NB * FSTR + NB * 4) * (int)sizeof(float);
    cudaFuncSetAttribute(fused_kernel,
                         cudaFuncAttributeMaxDynamicSharedMemorySize, dsmem);
    fused_kernel<<<NGRID, THREADS, dsmem>>>(
        features, geometry, w_in, w_h, w_out, lin_w, lin_b, (float*)d_out);
}